// round 12
// baseline (speedup 1.0000x reference)
#include <cuda_runtime.h>

// GravNet block:
//   feats  = x @ Wf + bf                      (B,N,22)
//   coords = x @ Ws + bs                      (B,N,4)
//   d2[n,m] = sq[n] + sq[m] - 2 <c_n, c_m>
//   top-40 smallest d2 per n (rank 0 = self, dropped)
//   w_j = exp(-10*|d2_j|); agg = [max_j(f_j*w_j), mean_j(f_j*w_j)]  (44)
//   out = tanh([x, agg] @ Wo + bo)            (B,N,48)

#define BB 8
#define NN 4096
#define FIN 32
#define PP 22
#define SS 4
#define FOUT 48
#define KSEL 40
#define FUPD (FIN + 2 * PP)   // 76
#define BUF 16

// ---- scratch (no allocations allowed) ----
__device__ float  g_feats[BB * NN * PP];
__device__ float4 g_coords[BB * NN];
__device__ float  g_sq[BB * NN];

// ============================================================
// Kernel 1: feats / coords / sq
// ============================================================
__global__ __launch_bounds__(128) void k_encode(
    const float* __restrict__ x,
    const float* __restrict__ Wf, const float* __restrict__ bf,
    const float* __restrict__ Ws, const float* __restrict__ bs)
{
    __shared__ float sWf[FIN * PP];
    __shared__ float sWs[FIN * SS];
    __shared__ float sbf[PP];
    __shared__ float sbs[SS];
    int tid = threadIdx.x;
    for (int i = tid; i < FIN * PP; i += 128) sWf[i] = Wf[i];
    for (int i = tid; i < FIN * SS; i += 128) sWs[i] = Ws[i];
    if (tid < PP) sbf[tid] = bf[tid];
    if (tid < SS) sbs[tid] = bs[tid];
    __syncthreads();

    int gid = blockIdx.x * 128 + tid;   // point id in [0, B*N)
    const float* xr = x + (size_t)gid * FIN;
    float xv[FIN];
#pragma unroll
    for (int i = 0; i < FIN / 4; i++) {
        float4 v = reinterpret_cast<const float4*>(xr)[i];
        xv[4 * i] = v.x; xv[4 * i + 1] = v.y; xv[4 * i + 2] = v.z; xv[4 * i + 3] = v.w;
    }

    float* fr = g_feats + (size_t)gid * PP;
#pragma unroll
    for (int p = 0; p < PP; p++) {
        float a = sbf[p];
#pragma unroll
        for (int i = 0; i < FIN; i++) a = fmaf(xv[i], sWf[i * PP + p], a);
        fr[p] = a;
    }

    float c0 = sbs[0], c1 = sbs[1], c2 = sbs[2], c3 = sbs[3];
#pragma unroll
    for (int i = 0; i < FIN; i++) {
        float xi = xv[i];
        c0 = fmaf(xi, sWs[i * SS + 0], c0);
        c1 = fmaf(xi, sWs[i * SS + 1], c1);
        c2 = fmaf(xi, sWs[i * SS + 2], c2);
        c3 = fmaf(xi, sWs[i * SS + 3], c3);
    }
    // sq with the SAME fma-chain pattern as the dot product in k_knn,
    // so the self-distance cancels to exactly 0.
    float sq = c0 * c0;
    sq = fmaf(c1, c1, sq);
    sq = fmaf(c2, c2, sq);
    sq = fmaf(c3, c3, sq);
    g_coords[gid] = make_float4(c0, c1, c2, c3);
    g_sq[gid] = sq;
}

// ============================================================
// Kernel 2: KNN scan + weighted max/mean aggregation + output GEMM + tanh
//   grid = (N/128, B), block = 128, one thread per query point.
//   smem: coords(float4 x 4096) | sq(4096) | Wo(76x48) | bo(48) = 96704 B
// ============================================================
__global__ __launch_bounds__(128) void k_knn(
    const float* __restrict__ x,
    const float* __restrict__ Wo, const float* __restrict__ bo,
    float* __restrict__ out)
{
    extern __shared__ float sm_[];
    float4* sc  = reinterpret_cast<float4*>(sm_);   // [NN]
    float*  ssq = sm_ + 4 * NN;                     // [NN]
    float*  sWo = ssq + NN;                         // [FUPD*FOUT]
    float*  sbo = sWo + FUPD * FOUT;                // [FOUT]

    int tid = threadIdx.x;
    int b = blockIdx.y;

    const float4* gc = g_coords + (size_t)b * NN;
    const float*  gs = g_sq + (size_t)b * NN;
    for (int i = tid; i < NN; i += 128) { sc[i] = gc[i]; ssq[i] = gs[i]; }
    for (int i = tid; i < FUPD * FOUT; i += 128) sWo[i] = Wo[i];
    if (tid < FOUT) sbo[tid] = bo[tid];
    __syncthreads();

    int nq = blockIdx.x * 128 + tid;       // query index within batch
    float4 mc = sc[nq];
    float mysq = ssq[nq];

    // sorted top-KSEL list (ascending by (d2, idx)); local memory
    float kd[KSEL]; int ki[KSEL];
#pragma unroll
    for (int j = 0; j < KSEL; j++) { kd[j] = 3.4e38f; ki[j] = -1; }
    float worst = 3.4e38f;

    // per-lane acceptance buffer, merged warp-synchronously
    float bd[BUF]; int bi[BUF];
    int cnt = 0;

#pragma unroll 4
    for (int m = 0; m < NN; m++) {
        float4 cm = sc[m];
        float t = mc.x * cm.x;
        t = fmaf(mc.y, cm.y, t);
        t = fmaf(mc.z, cm.z, t);
        t = fmaf(mc.w, cm.w, t);
        float d2 = fmaf(-2.0f, t, mysq + ssq[m]);   // exact 0 for m == nq

        if (d2 < worst) {          // strict: ties lose to earlier (smaller idx)
            bd[cnt] = d2; bi[cnt] = m; cnt++;
        }
        if (__ballot_sync(0xffffffffu, cnt == BUF)) {
            // batched merge of buffered candidates into sorted top-K
            for (int q = 0; q < cnt; q++) {
                float d = bd[q];
                if (d < kd[KSEL - 1]) {
                    int ii = bi[q];
                    int j = KSEL - 1;
#pragma unroll 1
                    while (j > 0 && kd[j - 1] > d) {
                        kd[j] = kd[j - 1]; ki[j] = ki[j - 1]; --j;
                    }
                    kd[j] = d; ki[j] = ii;
                }
            }
            cnt = 0;
            worst = kd[KSEL - 1];
        }
    }
    // final merge of leftovers
    for (int q = 0; q < cnt; q++) {
        float d = bd[q];
        if (d < kd[KSEL - 1]) {
            int ii = bi[q];
            int j = KSEL - 1;
#pragma unroll 1
            while (j > 0 && kd[j - 1] > d) {
                kd[j] = kd[j - 1]; ki[j] = ki[j - 1]; --j;
            }
            kd[j] = d; ki[j] = ii;
        }
    }

    // ---- aggregation over neighbors (ranks 1..39; rank 0 = self, dropped) ----
    float mx[PP], smn[PP];
#pragma unroll
    for (int p = 0; p < PP; p++) { mx[p] = -3.4e38f; smn[p] = 0.0f; }

    const float* fb = g_feats + (size_t)b * NN * PP;
    for (int j = 1; j < KSEL; j++) {
        int id = ki[j];
        float w = __expf(-10.0f * fabsf(kd[j]));
        const float2* fr = reinterpret_cast<const float2*>(fb + (size_t)id * PP);
#pragma unroll
        for (int h = 0; h < PP / 2; h++) {
            float2 v = fr[h];
            float a0 = v.x * w;
            float a1 = v.y * w;
            mx[2 * h]     = fmaxf(mx[2 * h], a0);     smn[2 * h]     += a0;
            mx[2 * h + 1] = fmaxf(mx[2 * h + 1], a1); smn[2 * h + 1] += a1;
        }
    }

    // ---- fused output GEMM: out = tanh([x(32), max(22), mean(22)] @ Wo + bo) ----
    float acc[FOUT];
#pragma unroll
    for (int o = 0; o < FOUT; o++) acc[o] = sbo[o];

    const float* xr = x + ((size_t)b * NN + nq) * FIN;
#pragma unroll
    for (int i = 0; i < FIN / 4; i++) {
        float4 v = reinterpret_cast<const float4*>(xr)[i];
        float xv4[4] = {v.x, v.y, v.z, v.w};
#pragma unroll
        for (int k = 0; k < 4; k++) {
            float vv = xv4[k];
            const float* wr = sWo + (4 * i + k) * FOUT;
#pragma unroll
            for (int o = 0; o < FOUT; o++) acc[o] = fmaf(vv, wr[o], acc[o]);
        }
    }
#pragma unroll
    for (int p = 0; p < PP; p++) {
        float vv = mx[p];
        const float* wr = sWo + (FIN + p) * FOUT;
#pragma unroll
        for (int o = 0; o < FOUT; o++) acc[o] = fmaf(vv, wr[o], acc[o]);
    }
    const float inv39 = 1.0f / 39.0f;
#pragma unroll
    for (int p = 0; p < PP; p++) {
        float vv = smn[p] * inv39;
        const float* wr = sWo + (FIN + PP + p) * FOUT;
#pragma unroll
        for (int o = 0; o < FOUT; o++) acc[o] = fmaf(vv, wr[o], acc[o]);
    }

    float4* o4 = reinterpret_cast<float4*>(out + ((size_t)b * NN + nq) * FOUT);
#pragma unroll
    for (int o = 0; o < FOUT / 4; o++) {
        o4[o] = make_float4(tanhf(acc[4 * o]), tanhf(acc[4 * o + 1]),
                            tanhf(acc[4 * o + 2]), tanhf(acc[4 * o + 3]));
    }
}

// ============================================================
extern "C" void kernel_launch(void* const* d_in, const int* in_sizes, int n_in,
                              void* d_out, int out_size)
{
    (void)in_sizes; (void)n_in; (void)out_size;
    const float* x  = (const float*)d_in[0];
    const float* Wf = (const float*)d_in[1];
    const float* bf = (const float*)d_in[2];
    const float* Ws = (const float*)d_in[3];
    const float* bs = (const float*)d_in[4];
    const float* Wo = (const float*)d_in[5];
    const float* bo = (const float*)d_in[6];
    float* out = (float*)d_out;

    k_encode<<<(BB * NN) / 128, 128>>>(x, Wf, bf, Ws, bs);

    size_t shmem = (size_t)(4 * NN + NN + FUPD * FOUT + FOUT) * sizeof(float); // 96704 B
    cudaFuncSetAttribute(k_knn, cudaFuncAttributeMaxDynamicSharedMemorySize, (int)shmem);
    dim3 grid(NN / 128, BB);
    k_knn<<<grid, 128, shmem>>>(x, Wo, bo, out);
}

// round 13
// speedup vs baseline: 1.3868x; 1.3868x over previous
#include <cuda_runtime.h>

// GravNet block:
//   feats  = x @ Wf + bf                      (B,N,22)
//   coords = x @ Ws + bs                      (B,N,4)
//   d2[n,m] = sq[n] + sq[m] - 2 <c_n, c_m>
//   top-40 smallest d2 per n (rank 0 = self, dropped) -> keep top-39 excluding self
//   w_j = exp(-10*|d2_j|); agg = [max_j(f_j*w_j), mean_j(f_j*w_j)]  (44)
//   out = tanh([x, agg] @ Wo + bo)            (B,N,48)

#define BB 8
#define NN 4096
#define FIN 32
#define PP 22
#define SS 4
#define FOUT 48
#define KNB 39                 // neighbors kept (K-1, self excluded by index)
#define FUPD (FIN + 2 * PP)    // 76

// ---- scratch (no allocations allowed) ----
__device__ float  g_feats[BB * NN * PP];
__device__ float4 g_coords[BB * NN];
__device__ float  g_sq[BB * NN];

// ============================================================
// Kernel 1: feats / coords / sq
// ============================================================
__global__ __launch_bounds__(128) void k_encode(
    const float* __restrict__ x,
    const float* __restrict__ Wf, const float* __restrict__ bf,
    const float* __restrict__ Ws, const float* __restrict__ bs)
{
    __shared__ float sWf[FIN * PP];
    __shared__ float sWs[FIN * SS];
    __shared__ float sbf[PP];
    __shared__ float sbs[SS];
    int tid = threadIdx.x;
    for (int i = tid; i < FIN * PP; i += 128) sWf[i] = Wf[i];
    for (int i = tid; i < FIN * SS; i += 128) sWs[i] = Ws[i];
    if (tid < PP) sbf[tid] = bf[tid];
    if (tid < SS) sbs[tid] = bs[tid];
    __syncthreads();

    int gid = blockIdx.x * 128 + tid;   // point id in [0, B*N)
    const float* xr = x + (size_t)gid * FIN;
    float xv[FIN];
#pragma unroll
    for (int i = 0; i < FIN / 4; i++) {
        float4 v = reinterpret_cast<const float4*>(xr)[i];
        xv[4 * i] = v.x; xv[4 * i + 1] = v.y; xv[4 * i + 2] = v.z; xv[4 * i + 3] = v.w;
    }

    float* fr = g_feats + (size_t)gid * PP;
#pragma unroll
    for (int p = 0; p < PP; p++) {
        float a = sbf[p];
#pragma unroll
        for (int i = 0; i < FIN; i++) a = fmaf(xv[i], sWf[i * PP + p], a);
        fr[p] = a;
    }

    float c0 = sbs[0], c1 = sbs[1], c2 = sbs[2], c3 = sbs[3];
#pragma unroll
    for (int i = 0; i < FIN; i++) {
        float xi = xv[i];
        c0 = fmaf(xi, sWs[i * SS + 0], c0);
        c1 = fmaf(xi, sWs[i * SS + 1], c1);
        c2 = fmaf(xi, sWs[i * SS + 2], c2);
        c3 = fmaf(xi, sWs[i * SS + 3], c3);
    }
    float sq = c0 * c0;
    sq = fmaf(c1, c1, sq);
    sq = fmaf(c2, c2, sq);
    sq = fmaf(c3, c3, sq);
    g_coords[gid] = make_float4(c0, c1, c2, c3);
    g_sq[gid] = sq;
}

// ============================================================
// Kernel 2: KNN scan (max-heap top-39) + weighted max/mean aggregation
//           + fused output GEMM + tanh
//   grid = (N/128, B), block = 128, one thread per query point.
//   smem: coords(float4 x 4096) | sq(4096) | Wo(76x48) | bo(48) = 96704 B
// ============================================================
__global__ __launch_bounds__(128) void k_knn(
    const float* __restrict__ x,
    const float* __restrict__ Wo, const float* __restrict__ bo,
    float* __restrict__ out)
{
    extern __shared__ float sm_[];
    float4* sc  = reinterpret_cast<float4*>(sm_);   // [NN]
    float*  ssq = sm_ + 4 * NN;                     // [NN]
    float*  sWo = ssq + NN;                         // [FUPD*FOUT]
    float*  sbo = sWo + FUPD * FOUT;                // [FOUT]

    int tid = threadIdx.x;
    int b = blockIdx.y;

    const float4* gc = g_coords + (size_t)b * NN;
    const float*  gs = g_sq + (size_t)b * NN;
    for (int i = tid; i < NN; i += 128) { sc[i] = gc[i]; ssq[i] = gs[i]; }
    for (int i = tid; i < FUPD * FOUT; i += 128) sWo[i] = Wo[i];
    if (tid < FOUT) sbo[tid] = bo[tid];
    __syncthreads();

    int nq = blockIdx.x * 128 + tid;       // query index within batch
    float4 mc = sc[nq];
    float mysq = ssq[nq];

    // max-heap of selection keys; key = sq[m] - 2*<c_n,c_m>  (d2 shifted by -sq[n])
    float hk[KNB]; int hix[KNB];
#pragma unroll
    for (int j = 0; j < KNB; j++) { hk[j] = 3.4e38f; hix[j] = 0; }
    float root = 3.4e38f;                  // cached heap max

#pragma unroll 4
    for (int m = 0; m < NN; m++) {
        float4 cm = sc[m];
        float t = mc.x * cm.x;
        t = fmaf(mc.y, cm.y, t);
        t = fmaf(mc.z, cm.z, t);
        t = fmaf(mc.w, cm.w, t);
        float key = fmaf(-2.0f, t, ssq[m]);

        if (key < root && m != nq) {
            // replace root, sift-down (max-heap, depth <= 6)
            int j = 0;
#pragma unroll 1
            for (;;) {
                int l = 2 * j + 1;
                if (l >= KNB) break;
                int r = l + 1;
                float cl = hk[l];
                float cr = (r < KNB) ? hk[r] : -3.4e38f;
                int   c  = (cr > cl) ? r : l;
                float cv = (cr > cl) ? cr : cl;
                if (cv <= key) break;
                hk[j] = cv; hix[j] = hix[c];
                j = c;
            }
            hk[j] = key; hix[j] = m;
            root = hk[0];
        }
    }

    // ---- aggregation over 39 neighbors (order-invariant max / mean) ----
    float mx[PP], smn[PP];
#pragma unroll
    for (int p = 0; p < PP; p++) { mx[p] = -3.4e38f; smn[p] = 0.0f; }

    const float* fb = g_feats + (size_t)b * NN * PP;
#pragma unroll 1
    for (int j = 0; j < KNB; j++) {
        int id = hix[j];
        float d2 = hk[j] + mysq;
        float w = __expf(-10.0f * fabsf(d2));
        const float2* fr = reinterpret_cast<const float2*>(fb + (size_t)id * PP);
#pragma unroll
        for (int h = 0; h < PP / 2; h++) {
            float2 v = fr[h];
            float a0 = v.x * w;
            float a1 = v.y * w;
            mx[2 * h]     = fmaxf(mx[2 * h], a0);     smn[2 * h]     += a0;
            mx[2 * h + 1] = fmaxf(mx[2 * h + 1], a1); smn[2 * h + 1] += a1;
        }
    }

    // ---- fused output GEMM: out = tanh([x(32), max(22), mean(22)] @ Wo + bo) ----
    float acc[FOUT];
#pragma unroll
    for (int o = 0; o < FOUT; o++) acc[o] = sbo[o];

    const float* xr = x + ((size_t)b * NN + nq) * FIN;
#pragma unroll
    for (int i = 0; i < FIN / 4; i++) {
        float4 v = reinterpret_cast<const float4*>(xr)[i];
        float xv4[4] = {v.x, v.y, v.z, v.w};
#pragma unroll
        for (int k = 0; k < 4; k++) {
            float vv = xv4[k];
            const float* wr = sWo + (4 * i + k) * FOUT;
#pragma unroll
            for (int o = 0; o < FOUT; o++) acc[o] = fmaf(vv, wr[o], acc[o]);
        }
    }
#pragma unroll
    for (int p = 0; p < PP; p++) {
        float vv = mx[p];
        const float* wr = sWo + (FIN + p) * FOUT;
#pragma unroll
        for (int o = 0; o < FOUT; o++) acc[o] = fmaf(vv, wr[o], acc[o]);
    }
    const float inv39 = 1.0f / 39.0f;
#pragma unroll
    for (int p = 0; p < PP; p++) {
        float vv = smn[p] * inv39;
        const float* wr = sWo + (FIN + PP + p) * FOUT;
#pragma unroll
        for (int o = 0; o < FOUT; o++) acc[o] = fmaf(vv, wr[o], acc[o]);
    }

    float4* o4 = reinterpret_cast<float4*>(out + ((size_t)b * NN + nq) * FOUT);
#pragma unroll
    for (int o = 0; o < FOUT / 4; o++) {
        o4[o] = make_float4(tanhf(acc[4 * o]), tanhf(acc[4 * o + 1]),
                            tanhf(acc[4 * o + 2]), tanhf(acc[4 * o + 3]));
    }
}

// ============================================================
extern "C" void kernel_launch(void* const* d_in, const int* in_sizes, int n_in,
                              void* d_out, int out_size)
{
    (void)in_sizes; (void)n_in; (void)out_size;
    const float* x  = (const float*)d_in[0];
    const float* Wf = (const float*)d_in[1];
    const float* bf = (const float*)d_in[2];
    const float* Ws = (const float*)d_in[3];
    const float* bs = (const float*)d_in[4];
    const float* Wo = (const float*)d_in[5];
    const float* bo = (const float*)d_in[6];
    float* out = (float*)d_out;

    k_encode<<<(BB * NN) / 128, 128>>>(x, Wf, bf, Ws, bs);

    size_t shmem = (size_t)(4 * NN + NN + FUPD * FOUT + FOUT) * sizeof(float); // 96704 B
    cudaFuncSetAttribute(k_knn, cudaFuncAttributeMaxDynamicSharedMemorySize, (int)shmem);
    dim3 grid(NN / 128, BB);
    k_knn<<<grid, 128, shmem>>>(x, Wo, bo, out);
}

// round 14
// speedup vs baseline: 13.9238x; 10.0404x over previous
#include <cuda_runtime.h>

// GravNet block:
//   feats  = x @ Wf + bf                      (B,N,22)
//   coords = x @ Ws + bs                      (B,N,4)
//   d2[n,m] = sq[n] + sq[m] - 2 <c_n, c_m>
//   top-40 smallest d2 per n (rank 0 = self, dropped) -> keep top-39 excluding self
//   w_j = exp(-10*|d2_j|); agg = [max_j(f_j*w_j), mean_j(f_j*w_j)]  (44)
//   out = tanh([x, agg] @ Wo + bo)            (B,N,48)

#define BB 8
#define NN 4096
#define FIN 32
#define PP 22
#define SS 4
#define FOUT 48
#define KNB 39                 // neighbors kept (K-1, self excluded by index)
#define FUPD (FIN + 2 * PP)    // 76
#define BUFN 8                 // merge trigger threshold
#define BUFC 12                // buffer capacity (BUFN + unroll slack 4)

// ---- scratch (no allocations allowed) ----
__device__ float  g_feats[BB * NN * PP];
__device__ float4 g_coords[BB * NN];
__device__ float  g_sq[BB * NN];

// ============================================================
// Kernel 1: feats / coords / sq
// ============================================================
__global__ __launch_bounds__(128) void k_encode(
    const float* __restrict__ x,
    const float* __restrict__ Wf, const float* __restrict__ bf,
    const float* __restrict__ Ws, const float* __restrict__ bs)
{
    __shared__ float sWf[FIN * PP];
    __shared__ float sWs[FIN * SS];
    __shared__ float sbf[PP];
    __shared__ float sbs[SS];
    int tid = threadIdx.x;
    for (int i = tid; i < FIN * PP; i += 128) sWf[i] = Wf[i];
    for (int i = tid; i < FIN * SS; i += 128) sWs[i] = Ws[i];
    if (tid < PP) sbf[tid] = bf[tid];
    if (tid < SS) sbs[tid] = bs[tid];
    __syncthreads();

    int gid = blockIdx.x * 128 + tid;   // point id in [0, B*N)
    const float* xr = x + (size_t)gid * FIN;
    float xv[FIN];
#pragma unroll
    for (int i = 0; i < FIN / 4; i++) {
        float4 v = reinterpret_cast<const float4*>(xr)[i];
        xv[4 * i] = v.x; xv[4 * i + 1] = v.y; xv[4 * i + 2] = v.z; xv[4 * i + 3] = v.w;
    }

    float* fr = g_feats + (size_t)gid * PP;
#pragma unroll
    for (int p = 0; p < PP; p++) {
        float a = sbf[p];
#pragma unroll
        for (int i = 0; i < FIN; i++) a = fmaf(xv[i], sWf[i * PP + p], a);
        fr[p] = a;
    }

    float c0 = sbs[0], c1 = sbs[1], c2 = sbs[2], c3 = sbs[3];
#pragma unroll
    for (int i = 0; i < FIN; i++) {
        float xi = xv[i];
        c0 = fmaf(xi, sWs[i * SS + 0], c0);
        c1 = fmaf(xi, sWs[i * SS + 1], c1);
        c2 = fmaf(xi, sWs[i * SS + 2], c2);
        c3 = fmaf(xi, sWs[i * SS + 3], c3);
    }
    float sq = c0 * c0;
    sq = fmaf(c1, c1, sq);
    sq = fmaf(c2, c2, sq);
    sq = fmaf(c3, c3, sq);
    g_coords[gid] = make_float4(c0, c1, c2, c3);
    g_sq[gid] = sq;
}

// Register-only predicated insertion ladder (static indexing throughout).
// kd ascending; strict '<' keeps earlier index on ties (matches top_k).
#define LADDER_INSERT(DV, IV)                                         \
    do {                                                              \
        float _d = (DV); int _i = (IV);                               \
        if (_d < kd[KNB - 1]) {                                       \
            _Pragma("unroll")                                         \
            for (int _j = KNB - 1; _j >= 1; --_j) {                   \
                bool _p  = _d < kd[_j];                               \
                bool _pp = _d < kd[_j - 1];                           \
                float _nk = _pp ? kd[_j - 1] : _d;                    \
                int   _ni = _pp ? ki[_j - 1] : _i;                    \
                kd[_j] = _p ? _nk : kd[_j];                           \
                ki[_j] = _p ? _ni : ki[_j];                           \
            }                                                         \
            if (_d < kd[0]) { kd[0] = _d; ki[0] = _i; }               \
        }                                                             \
    } while (0)

// ============================================================
// Kernel 2: KNN scan (buffered register-ladder top-39) + weighted
//           max/mean aggregation + fused output GEMM + tanh
//   grid = (N/128, B), block = 128, one thread per query point.
//   smem: coords(float4 x 4096) | sq(4096) | Wo(76x48) | bo(48) = 96704 B
// ============================================================
__global__ __launch_bounds__(128, 2) void k_knn(
    const float* __restrict__ x,
    const float* __restrict__ Wo, const float* __restrict__ bo,
    float* __restrict__ out)
{
    extern __shared__ float sm_[];
    float4* sc  = reinterpret_cast<float4*>(sm_);   // [NN]
    float*  ssq = sm_ + 4 * NN;                     // [NN]
    float*  sWo = ssq + NN;                         // [FUPD*FOUT]
    float*  sbo = sWo + FUPD * FOUT;                // [FOUT]

    int tid = threadIdx.x;
    int b = blockIdx.y;

    const float4* gc = g_coords + (size_t)b * NN;
    const float*  gs = g_sq + (size_t)b * NN;
    for (int i = tid; i < NN; i += 128) { sc[i] = gc[i]; ssq[i] = gs[i]; }
    for (int i = tid; i < FUPD * FOUT; i += 128) sWo[i] = Wo[i];
    if (tid < FOUT) sbo[tid] = bo[tid];
    __syncthreads();

    int nq = blockIdx.x * 128 + tid;       // query index within batch
    float4 mc = sc[nq];
    float mysq = ssq[nq];

    // sorted top-KNB of keys; key = sq[m] - 2*<c_n,c_m>  (d2 shifted by -sq[n])
    // REGISTER-resident: every access below is statically indexed.
    float kd[KNB]; int ki[KNB];
#pragma unroll
    for (int j = 0; j < KNB; j++) { kd[j] = 3.4e38f; ki[j] = 0; }

    // small acceptance buffer (local memory; stores only, loads batched)
    float bd[BUFC]; int bi[BUFC];
    int cnt = 0;
    float bound = 3.4e38f;      // stale copy of kd[KNB-1], refreshed at merges

    for (int m0 = 0; m0 < NN; m0 += 4) {
#pragma unroll
        for (int u = 0; u < 4; u++) {
            int m = m0 + u;
            float4 cm = sc[m];
            float t = mc.x * cm.x;
            t = fmaf(mc.y, cm.y, t);
            t = fmaf(mc.z, cm.z, t);
            t = fmaf(mc.w, cm.w, t);
            float key = fmaf(-2.0f, t, ssq[m]);   // same rounding as R13 (passed)
            if (key < bound && m != nq) { bd[cnt] = key; bi[cnt] = m; cnt++; }
        }
        if (__ballot_sync(0xffffffffu, cnt >= BUFN)) {
#pragma unroll 1
            for (int q = 0; q < cnt; q++) {
                LADDER_INSERT(bd[q], bi[q]);
            }
            cnt = 0;
            bound = kd[KNB - 1];
        }
    }
    // tail: merge leftovers
#pragma unroll 1
    for (int q = 0; q < cnt; q++) {
        LADDER_INSERT(bd[q], bi[q]);
    }

    // ---- aggregation over 39 neighbors (fully unrolled: kd/ki stay in regs) ----
    float mx[PP], smn[PP];
#pragma unroll
    for (int p = 0; p < PP; p++) { mx[p] = -3.4e38f; smn[p] = 0.0f; }

    const float* fb = g_feats + (size_t)b * NN * PP;
#pragma unroll
    for (int j = 0; j < KNB; j++) {
        int id = ki[j];
        float d2 = kd[j] + mysq;
        float w = __expf(-10.0f * fabsf(d2));
        const float2* fr = reinterpret_cast<const float2*>(fb + (size_t)id * PP);
#pragma unroll
        for (int h = 0; h < PP / 2; h++) {
            float2 v = fr[h];
            float a0 = v.x * w;
            float a1 = v.y * w;
            mx[2 * h]     = fmaxf(mx[2 * h], a0);     smn[2 * h]     += a0;
            mx[2 * h + 1] = fmaxf(mx[2 * h + 1], a1); smn[2 * h + 1] += a1;
        }
    }

    // ---- fused output GEMM: out = tanh([x(32), max(22), mean(22)] @ Wo + bo) ----
    float acc[FOUT];
#pragma unroll
    for (int o = 0; o < FOUT; o++) acc[o] = sbo[o];

    const float* xr = x + ((size_t)b * NN + nq) * FIN;
#pragma unroll 1
    for (int i = 0; i < FIN / 4; i++) {
        float4 v = reinterpret_cast<const float4*>(xr)[i];
        float xv4[4] = {v.x, v.y, v.z, v.w};
#pragma unroll
        for (int k = 0; k < 4; k++) {
            float vv = xv4[k];
            const float* wr = sWo + (4 * i + k) * FOUT;
#pragma unroll
            for (int o = 0; o < FOUT; o++) acc[o] = fmaf(vv, wr[o], acc[o]);
        }
    }
#pragma unroll 1
    for (int p = 0; p < PP; p++) {
        float vv = mx[p];
        const float* wr = sWo + (FIN + p) * FOUT;
#pragma unroll
        for (int o = 0; o < FOUT; o++) acc[o] = fmaf(vv, wr[o], acc[o]);
    }
    const float inv39 = 1.0f / 39.0f;
#pragma unroll 1
    for (int p = 0; p < PP; p++) {
        float vv = smn[p] * inv39;
        const float* wr = sWo + (FIN + PP + p) * FOUT;
#pragma unroll
        for (int o = 0; o < FOUT; o++) acc[o] = fmaf(vv, wr[o], acc[o]);
    }

    float4* o4 = reinterpret_cast<float4*>(out + ((size_t)b * NN + nq) * FOUT);
#pragma unroll
    for (int o = 0; o < FOUT / 4; o++) {
        o4[o] = make_float4(tanhf(acc[4 * o]), tanhf(acc[4 * o + 1]),
                            tanhf(acc[4 * o + 2]), tanhf(acc[4 * o + 3]));
    }
}

// ============================================================
extern "C" void kernel_launch(void* const* d_in, const int* in_sizes, int n_in,
                              void* d_out, int out_size)
{
    (void)in_sizes; (void)n_in; (void)out_size;
    const float* x  = (const float*)d_in[0];
    const float* Wf = (const float*)d_in[1];
    const float* bf = (const float*)d_in[2];
    const float* Ws = (const float*)d_in[3];
    const float* bs = (const float*)d_in[4];
    const float* Wo = (const float*)d_in[5];
    const float* bo = (const float*)d_in[6];
    float* out = (float*)d_out;

    k_encode<<<(BB * NN) / 128, 128>>>(x, Wf, bf, Ws, bs);

    size_t shmem = (size_t)(4 * NN + NN + FUPD * FOUT + FOUT) * sizeof(float); // 96704 B
    cudaFuncSetAttribute(k_knn, cudaFuncAttributeMaxDynamicSharedMemorySize, (int)shmem);
    dim3 grid(NN / 128, BB);
    k_knn<<<grid, 128, shmem>>>(x, Wo, bo, out);
}

// round 15
// speedup vs baseline: 13.9591x; 1.0025x over previous
#include <cuda_runtime.h>

// GravNet block:
//   feats  = x @ Wf + bf                      (B,N,22)
//   coords = x @ Ws + bs                      (B,N,4)
//   d2[n,m] = sq[n] + sq[m] - 2 <c_n, c_m>
//   top-40 smallest d2 per n (rank 0 = self, dropped) -> keep top-39 excluding self
//   w_j = exp(-10*|d2_j|); agg = [max_j(f_j*w_j), mean_j(f_j*w_j)]  (44)
//   out = tanh([x, agg] @ Wo + bo)            (B,N,48)

#define BB 8
#define NN 4096
#define FIN 32
#define PP 22
#define SS 4
#define FOUT 48
#define KNB 39                 // neighbors kept (K-1, self excluded by index)
#define FUPD (FIN + 2 * PP)    // 76
#define BUFN 8                 // merge trigger threshold
#define BUFC 12                // buffer capacity (BUFN + unroll slack 4)

// ---- scratch (no allocations allowed) ----
__device__ float  g_feats[BB * NN * PP];
__device__ float4 g_coords[BB * NN];
__device__ float  g_sq[BB * NN];

// ============================================================
// Kernel 1: feats / coords / sq
// ============================================================
__global__ __launch_bounds__(128) void k_encode(
    const float* __restrict__ x,
    const float* __restrict__ Wf, const float* __restrict__ bf,
    const float* __restrict__ Ws, const float* __restrict__ bs)
{
    __shared__ float sWf[FIN * PP];
    __shared__ float sWs[FIN * SS];
    __shared__ float sbf[PP];
    __shared__ float sbs[SS];
    int tid = threadIdx.x;
    for (int i = tid; i < FIN * PP; i += 128) sWf[i] = Wf[i];
    for (int i = tid; i < FIN * SS; i += 128) sWs[i] = Ws[i];
    if (tid < PP) sbf[tid] = bf[tid];
    if (tid < SS) sbs[tid] = bs[tid];
    __syncthreads();

    int gid = blockIdx.x * 128 + tid;   // point id in [0, B*N)
    const float* xr = x + (size_t)gid * FIN;
    float xv[FIN];
#pragma unroll
    for (int i = 0; i < FIN / 4; i++) {
        float4 v = reinterpret_cast<const float4*>(xr)[i];
        xv[4 * i] = v.x; xv[4 * i + 1] = v.y; xv[4 * i + 2] = v.z; xv[4 * i + 3] = v.w;
    }

    float* fr = g_feats + (size_t)gid * PP;
#pragma unroll
    for (int p = 0; p < PP; p++) {
        float a = sbf[p];
#pragma unroll
        for (int i = 0; i < FIN; i++) a = fmaf(xv[i], sWf[i * PP + p], a);
        fr[p] = a;
    }

    float c0 = sbs[0], c1 = sbs[1], c2 = sbs[2], c3 = sbs[3];
#pragma unroll
    for (int i = 0; i < FIN; i++) {
        float xi = xv[i];
        c0 = fmaf(xi, sWs[i * SS + 0], c0);
        c1 = fmaf(xi, sWs[i * SS + 1], c1);
        c2 = fmaf(xi, sWs[i * SS + 2], c2);
        c3 = fmaf(xi, sWs[i * SS + 3], c3);
    }
    float sq = c0 * c0;
    sq = fmaf(c1, c1, sq);
    sq = fmaf(c2, c2, sq);
    sq = fmaf(c3, c3, sq);
    g_coords[gid] = make_float4(c0, c1, c2, c3);
    g_sq[gid] = sq;
}

// Register-only predicated insertion ladder (static indexing throughout).
// kd ascending; strict '<' keeps earlier index on ties (matches top_k).
#define LADDER_INSERT(DV, IV)                                         \
    do {                                                              \
        float _d = (DV); int _i = (IV);                               \
        if (_d < kd[KNB - 1]) {                                       \
            _Pragma("unroll")                                         \
            for (int _j = KNB - 1; _j >= 1; --_j) {                   \
                bool _p  = _d < kd[_j];                               \
                bool _pp = _d < kd[_j - 1];                           \
                float _nk = _pp ? kd[_j - 1] : _d;                    \
                int   _ni = _pp ? ki[_j - 1] : _i;                    \
                kd[_j] = _p ? _nk : kd[_j];                           \
                ki[_j] = _p ? _ni : ki[_j];                           \
            }                                                         \
            if (_d < kd[0]) { kd[0] = _d; ki[0] = _i; }               \
        }                                                             \
    } while (0)

// ============================================================
// Kernel 2: KNN scan (buffered register-ladder top-39) + weighted
//           max/mean aggregation + fused output GEMM + tanh
//   grid = (N/128, B), block = 128, one thread per query point.
//   smem: coords(float4 x 4096) | sq(4096) | Wo(76x48) | bo(48) = 96704 B
// ============================================================
__global__ __launch_bounds__(128, 2) void k_knn(
    const float* __restrict__ x,
    const float* __restrict__ Wo, const float* __restrict__ bo,
    float* __restrict__ out)
{
    extern __shared__ float sm_[];
    float4* sc  = reinterpret_cast<float4*>(sm_);   // [NN]
    float*  ssq = sm_ + 4 * NN;                     // [NN]
    float*  sWo = ssq + NN;                         // [FUPD*FOUT]
    float*  sbo = sWo + FUPD * FOUT;                // [FOUT]

    int tid = threadIdx.x;
    int b = blockIdx.y;

    const float4* gc = g_coords + (size_t)b * NN;
    const float*  gs = g_sq + (size_t)b * NN;
    for (int i = tid; i < NN; i += 128) { sc[i] = gc[i]; ssq[i] = gs[i]; }
    for (int i = tid; i < FUPD * FOUT; i += 128) sWo[i] = Wo[i];
    if (tid < FOUT) sbo[tid] = bo[tid];
    __syncthreads();

    int nq = blockIdx.x * 128 + tid;       // query index within batch
    float4 mc = sc[nq];
    float mysq = ssq[nq];

    // sorted top-KNB of keys; key = sq[m] - 2*<c_n,c_m>  (d2 shifted by -sq[n])
    // REGISTER-resident: every access below is statically indexed.
    float kd[KNB]; int ki[KNB];
#pragma unroll
    for (int j = 0; j < KNB; j++) { kd[j] = 3.4e38f; ki[j] = 0; }

    // small acceptance buffer (local memory; stores only, loads batched)
    float bd[BUFC]; int bi[BUFC];
    int cnt = 0;
    float bound = 3.4e38f;      // stale copy of kd[KNB-1], refreshed at merges

    for (int m0 = 0; m0 < NN; m0 += 4) {
#pragma unroll
        for (int u = 0; u < 4; u++) {
            int m = m0 + u;
            float4 cm = sc[m];
            float t = mc.x * cm.x;
            t = fmaf(mc.y, cm.y, t);
            t = fmaf(mc.z, cm.z, t);
            t = fmaf(mc.w, cm.w, t);
            float key = fmaf(-2.0f, t, ssq[m]);   // same rounding as R13 (passed)
            if (key < bound && m != nq) { bd[cnt] = key; bi[cnt] = m; cnt++; }
        }
        if (__ballot_sync(0xffffffffu, cnt >= BUFN)) {
#pragma unroll 1
            for (int q = 0; q < cnt; q++) {
                LADDER_INSERT(bd[q], bi[q]);
            }
            cnt = 0;
            bound = kd[KNB - 1];
        }
    }
    // tail: merge leftovers
#pragma unroll 1
    for (int q = 0; q < cnt; q++) {
        LADDER_INSERT(bd[q], bi[q]);
    }

    // ---- aggregation over 39 neighbors (fully unrolled: kd/ki stay in regs) ----
    float mx[PP], smn[PP];
#pragma unroll
    for (int p = 0; p < PP; p++) { mx[p] = -3.4e38f; smn[p] = 0.0f; }

    const float* fb = g_feats + (size_t)b * NN * PP;
#pragma unroll
    for (int j = 0; j < KNB; j++) {
        int id = ki[j];
        float d2 = kd[j] + mysq;
        float w = __expf(-10.0f * fabsf(d2));
        const float2* fr = reinterpret_cast<const float2*>(fb + (size_t)id * PP);
#pragma unroll
        for (int h = 0; h < PP / 2; h++) {
            float2 v = fr[h];
            float a0 = v.x * w;
            float a1 = v.y * w;
            mx[2 * h]     = fmaxf(mx[2 * h], a0);     smn[2 * h]     += a0;
            mx[2 * h + 1] = fmaxf(mx[2 * h + 1], a1); smn[2 * h + 1] += a1;
        }
    }

    // ---- fused output GEMM: out = tanh([x(32), max(22), mean(22)] @ Wo + bo) ----
    float acc[FOUT];
#pragma unroll
    for (int o = 0; o < FOUT; o++) acc[o] = sbo[o];

    const float* xr = x + ((size_t)b * NN + nq) * FIN;
#pragma unroll 1
    for (int i = 0; i < FIN / 4; i++) {
        float4 v = reinterpret_cast<const float4*>(xr)[i];
        float xv4[4] = {v.x, v.y, v.z, v.w};
#pragma unroll
        for (int k = 0; k < 4; k++) {
            float vv = xv4[k];
            const float* wr = sWo + (4 * i + k) * FOUT;
#pragma unroll
            for (int o = 0; o < FOUT; o++) acc[o] = fmaf(vv, wr[o], acc[o]);
        }
    }
#pragma unroll 1
    for (int p = 0; p < PP; p++) {
        float vv = mx[p];
        const float* wr = sWo + (FIN + p) * FOUT;
#pragma unroll
        for (int o = 0; o < FOUT; o++) acc[o] = fmaf(vv, wr[o], acc[o]);
    }
    const float inv39 = 1.0f / 39.0f;
#pragma unroll 1
    for (int p = 0; p < PP; p++) {
        float vv = smn[p] * inv39;
        const float* wr = sWo + (FIN + PP + p) * FOUT;
#pragma unroll
        for (int o = 0; o < FOUT; o++) acc[o] = fmaf(vv, wr[o], acc[o]);
    }

    float4* o4 = reinterpret_cast<float4*>(out + ((size_t)b * NN + nq) * FOUT);
#pragma unroll
    for (int o = 0; o < FOUT / 4; o++) {
        o4[o] = make_float4(tanhf(acc[4 * o]), tanhf(acc[4 * o + 1]),
                            tanhf(acc[4 * o + 2]), tanhf(acc[4 * o + 3]));
    }
}

// ============================================================
extern "C" void kernel_launch(void* const* d_in, const int* in_sizes, int n_in,
                              void* d_out, int out_size)
{
    (void)in_sizes; (void)n_in; (void)out_size;
    const float* x  = (const float*)d_in[0];
    const float* Wf = (const float*)d_in[1];
    const float* bf = (const float*)d_in[2];
    const float* Ws = (const float*)d_in[3];
    const float* bs = (const float*)d_in[4];
    const float* Wo = (const float*)d_in[5];
    const float* bo = (const float*)d_in[6];
    float* out = (float*)d_out;

    k_encode<<<(BB * NN) / 128, 128>>>(x, Wf, bf, Ws, bs);

    size_t shmem = (size_t)(4 * NN + NN + FUPD * FOUT + FOUT) * sizeof(float); // 96704 B
    cudaFuncSetAttribute(k_knn, cudaFuncAttributeMaxDynamicSharedMemorySize, (int)shmem);
    dim3 grid(NN / 128, BB);
    k_knn<<<grid, 128, shmem>>>(x, Wo, bo, out);
}